// round 9
// baseline (speedup 1.0000x reference)
#include <cuda_runtime.h>

// Invert4_10: 16-step spiking scan, elementwise over fp32.
//   spike((v-T)/(|v|+1)) == (v > T)   (denominator strictly positive)
//   out(|x|) is PIECEWISE CONSTANT in a=|x|: for a < 3.75 the decision tree
//   has only ~7 leaves (enumerated bit-exactly at compile time). Rare a>=3.75
//   (P~1.8e-4/elem) -> exact predicated scan behind a warp-uniform vote.
// R9: vpt=1 (MLP_p1=1) -> cross-CTA L1tex-queue spread at its 1.10 floor
//     (R8 confirmed the spread model: vpt 4->2 gave -2.5us, DRAM 83.6->85.1%).
//     Vote granularity 128 elems -> slow-warp fraction ~2.2%.

// ---------------------------------------------------------------------------
// Compile-time exact decision-tree enumeration (fp32 bit-exact).
// ---------------------------------------------------------------------------
namespace ct {

constexpr float Hc[16] = {-0.00181154f, 0.8721661f, 0.9177631f, 0.9392744f,
                          0.5681609f, 0.9465831f, 0.6847087f, 0.45589155f,
                          0.57916474f, 0.7803396f, 0.28270212f, 0.49239117f,
                          1.1224731f, 0.5738949f, 0.32048506f, 0.2620882f};
constexpr float Dc[16] = {0.0931013f, 0.09543603f, -0.00957536f, -0.02775419f,
                          0.07635077f, -0.02604962f, -0.01608226f, -0.0154707f,
                          -0.01741009f, -0.00761568f, -0.00868225f, -0.01600825f,
                          -0.00795393f, -0.0046836f, -0.00339996f, -0.00177163f};
constexpr float Tc[16] = {-0.25367174f, -0.35691947f, 0.35702407f, 1.8097845f,
                          -0.8933508f, 0.74517566f, 0.57702994f, 0.56928945f,
                          0.61470956f, 0.43903926f, 0.20668195f, 0.6593264f,
                          0.35631987f, 0.15981139f, -0.12464668f, -0.22194518f};

constexpr float CUT = 3.75f;          // runtime slow-path threshold (a >= CUT)
constexpr int MAXL = 64;

constexpr double p2(int e) {
    double r = 1.0;
    if (e >= 0) { for (int i = 0; i < e;  ++i) r *= 2.0; }
    else        { for (int i = 0; i < -e; ++i) r *= 0.5; }
    return r;
}
constexpr float b2f(unsigned u) {
    int e = (int)((u >> 23) & 0xFFu);
    unsigned m = u & 0x7FFFFFu;
    double val = (e == 0) ? (double)m * p2(-149)
                          : (double)(m | 0x800000u) * p2(e - 150);
    return (float)val;
}

struct Chain { float c[16]; int n; };
constexpr float evalv(float a, const Chain& ch) {
    float v = a;
    for (int i = 0; i < ch.n; ++i) v = v - ch.c[i];
    return v;
}

struct Table { float lb[MAXL]; float val[MAXL]; int n; bool ok; };

constexpr void rec(Table& tb, int t, int zprev, Chain ch, float out,
                   unsigned lo, unsigned hi) {
    if (!tb.ok) return;
    if (b2f(lo) >= CUT) return;                 // covered by runtime slow path
    if (t == 16) {
        if (tb.n >= MAXL) { tb.ok = false; return; }
        tb.lb[tb.n] = b2f(lo);
        tb.val[tb.n] = out;
        tb.n++;
        return;
    }
    if (zprev) { ch.c[ch.n] = Hc[t]; ch.n++; }
    const float Tt = Tc[t];
    if (evalv(b2f(lo), ch) > Tt) {
        rec(tb, t + 1, 1, ch, out + Dc[t], lo, hi);
        return;
    }
    if (evalv(b2f(hi), ch) <= Tt) {
        rec(tb, t + 1, 0, ch, out, lo, hi);
        return;
    }
    unsigned s_lo = lo, s_hi = hi;
    while (s_hi - s_lo > 1u) {
        unsigned mid = s_lo + (s_hi - s_lo) / 2u;
        if (evalv(b2f(mid), ch) <= Tt) s_lo = mid; else s_hi = mid;
    }
    rec(tb, t + 1, 0, ch, out, lo, s_lo);
    rec(tb, t + 1, 1, ch, out + Dc[t], s_hi, hi);
}

constexpr Table build() {
    Table tb{};
    tb.n = 0; tb.ok = true;
    Chain ch{}; ch.n = 0;
    rec(tb, 0, 0, ch, 0.0f, 0u, 0x40800000u /* 4.0f */);
    return tb;
}

constexpr Table TBL = build();
static_assert(TBL.ok, "leaf table overflow");
static_assert(TBL.n >= 3 && TBL.n <= 24, "unexpected leaf count");

} // namespace ct

// ---------------------------------------------------------------------------
// Fast path: unrolled compare/select over compile-time leaves (immediates).
// ---------------------------------------------------------------------------
template <int J, int N> struct Sel {
    static __device__ __forceinline__ void go(float a, float& out) {
        constexpr float lb = ct::TBL.lb[J];
        constexpr float vl = ct::TBL.val[J];
        out = (a >= lb) ? vl : out;             // FSETP + FSEL, imm operands
        Sel<J + 1, N>::go(a, out);
    }
};
template <int N> struct Sel<N, N> {
    static __device__ __forceinline__ void go(float, float&) {}
};

static __device__ __forceinline__ float run1_table(float x) {
    float a = fabsf(x);
    float out = ct::TBL.val[0];
    Sel<1, ct::TBL.n>::go(a, out);
    float r = copysignf(out, x);                // LOP3
    return (x == 0.0f) ? 0.0f : r;              // jnp.sign(0) == 0
}

// ---------------------------------------------------------------------------
// Slow path: exact predicated scan (rel_err == 0 proven).
// ---------------------------------------------------------------------------
#define STEP(Tt, Dt, nHn)                              \
  asm("{\n\t.reg .pred p;\n\t"                         \
      "setp.gt.f32 p, %0, " #Tt ";\n\t"                \
      "@p add.f32 %1, %1, " #Dt ";\n\t"                \
      "@p add.f32 %0, %0, " #nHn ";\n\t}"              \
      : "+f"(v), "+f"(out))
#define LAST(Tt, Dt)                                   \
  asm("{\n\t.reg .pred p;\n\t"                         \
      "setp.gt.f32 p, %0, " #Tt ";\n\t"                \
      "@p add.f32 %1, %1, " #Dt ";\n\t}"               \
      : "+f"(v), "+f"(out))

static __device__ __forceinline__ float run1_scan(float x) {
    float v = fabsf(x) - 0.8721661f;    // peeled step 0 (z0=1): v = |x| - h1
    float out = 0.0931013f;             // d0
    STEP(-0.35691947,  0.09543603, -0.9177631);
    STEP( 0.35702407, -0.00957536, -0.9392744);
    STEP( 1.8097845,  -0.02775419, -0.5681609);
    STEP(-0.8933508,   0.07635077, -0.9465831);
    STEP( 0.74517566, -0.02604962, -0.6847087);
    STEP( 0.57702994, -0.01608226, -0.45589155);
    STEP( 0.56928945, -0.0154707,  -0.57916474);
    STEP( 0.61470956, -0.01741009, -0.7803396);
    STEP( 0.43903926, -0.00761568, -0.28270212);
    STEP( 0.20668195, -0.00868225, -0.49239117);
    STEP( 0.6593264,  -0.01600825, -1.1224731);
    STEP( 0.35631987, -0.00795393, -0.5738949);
    STEP( 0.15981139, -0.0046836,  -0.32048506);
    STEP(-0.12464668, -0.00339996, -0.2620882);
    LAST(-0.22194518, -0.00177163);
    float r = copysignf(out, x);
    return (x == 0.0f) ? 0.0f : r;
}

static __device__ __forceinline__ float4 run4_table(float4 p) {
    float4 r;
    r.x = run1_table(p.x); r.y = run1_table(p.y);
    r.z = run1_table(p.z); r.w = run1_table(p.w);
    return r;
}
static __device__ __forceinline__ float4 run4_scan(float4 p) {
    float4 r;
    r.x = run1_scan(p.x); r.y = run1_scan(p.y);
    r.z = run1_scan(p.z); r.w = run1_scan(p.w);
    return r;
}

static __device__ __forceinline__ float amax4(float4 p) {
    return fmaxf(fmaxf(fabsf(p.x), fabsf(p.y)), fmaxf(fabsf(p.z), fabsf(p.w)));
}

// Exact-cover variant: grid covers nvec exactly, no bounds checks. 1 float4/thread.
__global__ void __launch_bounds__(256)
invert_kernel_exact(const float4* __restrict__ x, float4* __restrict__ y) {
    const int i = blockIdx.x * blockDim.x + threadIdx.x;

    // Single streaming load per thread (MLP_p1=1 -> spread floor); .cs
    float4 a0 = __ldcs(x + i);

    // Warp-uniform path select: slow warp iff ANY of its 128 elems >= CUT.
    if (__any_sync(0xFFFFFFFFu, amax4(a0) >= ct::CUT)) {
        __stcs(y + i, run4_scan(a0));
    } else {
        __stcs(y + i, run4_table(a0));
    }
}

// Guarded fallback for non-divisible sizes (exact scan everywhere; rare).
__global__ void __launch_bounds__(256)
invert_kernel_guard(const float4* __restrict__ x, float4* __restrict__ y, int nvec) {
    const int i = blockIdx.x * blockDim.x + threadIdx.x;
    if (i < nvec) {
        float4 a0 = __ldcs(x + i);
        __stcs(y + i, run4_scan(a0));
    }
}

__global__ void invert_tail_kernel(const float* __restrict__ x, float* __restrict__ y,
                                   int start, int n) {
    int i = start + blockIdx.x * blockDim.x + threadIdx.x;
    if (i < n) y[i] = run1_scan(x[i]);
}

extern "C" void kernel_launch(void* const* d_in, const int* in_sizes, int n_in,
                              void* d_out, int out_size) {
    const float* x = (const float*)d_in[0];
    float* y = (float*)d_out;
    const long long n = (long long)in_sizes[0];

    const long long nvec = n >> 2;        // float4 count
    const int threads = 256;
    const long long per_blk = (long long)threads;   // vpt = 1

    if (nvec > 0 && (nvec % per_blk) == 0) {
        invert_kernel_exact<<<(unsigned)(nvec / per_blk), threads>>>(
            (const float4*)x, (float4*)y);
    } else if (nvec > 0) {
        long long blocks = (nvec + per_blk - 1) / per_blk;
        invert_kernel_guard<<<(unsigned)blocks, threads>>>(
            (const float4*)x, (float4*)y, (int)nvec);
    }

    const int rem = (int)(n & 3LL);
    if (rem) {
        invert_tail_kernel<<<1, 32>>>(x, y, (int)(n - rem), (int)n);
    }
}

// round 10
// speedup vs baseline: 1.0594x; 1.0594x over previous
#include <cuda_runtime.h>

// Invert4_10: 16-step spiking scan, elementwise over fp32.
//   spike((v-T)/(|v|+1)) == (v > T)   (denominator strictly positive)
//   out(|x|) is PIECEWISE CONSTANT in a=|x|: for a < 3.75 the decision tree
//   has only ~7 leaves (enumerated bit-exactly at compile time). Rare a>=3.75
//   (P~1.8e-4/elem) -> exact predicated scan behind a warp-uniform vote.
// R10: vpt=2 (measured MLP optimum: vpt=1 under-covers latency, vpt=4
//      over-queues), block 512 -> 4 CTAs/SM so oe*MLP_p1 = 8 < Q_th=16,
//      pushing cross-CTA L1tex wave spread to its floor. Otherwise == R8.

// ---------------------------------------------------------------------------
// Compile-time exact decision-tree enumeration (fp32 bit-exact).
// ---------------------------------------------------------------------------
namespace ct {

constexpr float Hc[16] = {-0.00181154f, 0.8721661f, 0.9177631f, 0.9392744f,
                          0.5681609f, 0.9465831f, 0.6847087f, 0.45589155f,
                          0.57916474f, 0.7803396f, 0.28270212f, 0.49239117f,
                          1.1224731f, 0.5738949f, 0.32048506f, 0.2620882f};
constexpr float Dc[16] = {0.0931013f, 0.09543603f, -0.00957536f, -0.02775419f,
                          0.07635077f, -0.02604962f, -0.01608226f, -0.0154707f,
                          -0.01741009f, -0.00761568f, -0.00868225f, -0.01600825f,
                          -0.00795393f, -0.0046836f, -0.00339996f, -0.00177163f};
constexpr float Tc[16] = {-0.25367174f, -0.35691947f, 0.35702407f, 1.8097845f,
                          -0.8933508f, 0.74517566f, 0.57702994f, 0.56928945f,
                          0.61470956f, 0.43903926f, 0.20668195f, 0.6593264f,
                          0.35631987f, 0.15981139f, -0.12464668f, -0.22194518f};

constexpr float CUT = 3.75f;          // runtime slow-path threshold (a >= CUT)
constexpr int MAXL = 64;

constexpr double p2(int e) {
    double r = 1.0;
    if (e >= 0) { for (int i = 0; i < e;  ++i) r *= 2.0; }
    else        { for (int i = 0; i < -e; ++i) r *= 0.5; }
    return r;
}
constexpr float b2f(unsigned u) {
    int e = (int)((u >> 23) & 0xFFu);
    unsigned m = u & 0x7FFFFFu;
    double val = (e == 0) ? (double)m * p2(-149)
                          : (double)(m | 0x800000u) * p2(e - 150);
    return (float)val;
}

struct Chain { float c[16]; int n; };
constexpr float evalv(float a, const Chain& ch) {
    float v = a;
    for (int i = 0; i < ch.n; ++i) v = v - ch.c[i];
    return v;
}

struct Table { float lb[MAXL]; float val[MAXL]; int n; bool ok; };

constexpr void rec(Table& tb, int t, int zprev, Chain ch, float out,
                   unsigned lo, unsigned hi) {
    if (!tb.ok) return;
    if (b2f(lo) >= CUT) return;                 // covered by runtime slow path
    if (t == 16) {
        if (tb.n >= MAXL) { tb.ok = false; return; }
        tb.lb[tb.n] = b2f(lo);
        tb.val[tb.n] = out;
        tb.n++;
        return;
    }
    if (zprev) { ch.c[ch.n] = Hc[t]; ch.n++; }
    const float Tt = Tc[t];
    if (evalv(b2f(lo), ch) > Tt) {
        rec(tb, t + 1, 1, ch, out + Dc[t], lo, hi);
        return;
    }
    if (evalv(b2f(hi), ch) <= Tt) {
        rec(tb, t + 1, 0, ch, out, lo, hi);
        return;
    }
    unsigned s_lo = lo, s_hi = hi;
    while (s_hi - s_lo > 1u) {
        unsigned mid = s_lo + (s_hi - s_lo) / 2u;
        if (evalv(b2f(mid), ch) <= Tt) s_lo = mid; else s_hi = mid;
    }
    rec(tb, t + 1, 0, ch, out, lo, s_lo);
    rec(tb, t + 1, 1, ch, out + Dc[t], s_hi, hi);
}

constexpr Table build() {
    Table tb{};
    tb.n = 0; tb.ok = true;
    Chain ch{}; ch.n = 0;
    rec(tb, 0, 0, ch, 0.0f, 0u, 0x40800000u /* 4.0f */);
    return tb;
}

constexpr Table TBL = build();
static_assert(TBL.ok, "leaf table overflow");
static_assert(TBL.n >= 3 && TBL.n <= 24, "unexpected leaf count");

} // namespace ct

// ---------------------------------------------------------------------------
// Fast path: unrolled compare/select over compile-time leaves (immediates).
// ---------------------------------------------------------------------------
template <int J, int N> struct Sel {
    static __device__ __forceinline__ void go(float a, float& out) {
        constexpr float lb = ct::TBL.lb[J];
        constexpr float vl = ct::TBL.val[J];
        out = (a >= lb) ? vl : out;             // FSETP + FSEL, imm operands
        Sel<J + 1, N>::go(a, out);
    }
};
template <int N> struct Sel<N, N> {
    static __device__ __forceinline__ void go(float, float&) {}
};

static __device__ __forceinline__ float run1_table(float x) {
    float a = fabsf(x);
    float out = ct::TBL.val[0];
    Sel<1, ct::TBL.n>::go(a, out);
    float r = copysignf(out, x);                // LOP3
    return (x == 0.0f) ? 0.0f : r;              // jnp.sign(0) == 0
}

// ---------------------------------------------------------------------------
// Slow path: exact predicated scan (rel_err == 0 proven).
// ---------------------------------------------------------------------------
#define STEP(Tt, Dt, nHn)                              \
  asm("{\n\t.reg .pred p;\n\t"                         \
      "setp.gt.f32 p, %0, " #Tt ";\n\t"                \
      "@p add.f32 %1, %1, " #Dt ";\n\t"                \
      "@p add.f32 %0, %0, " #nHn ";\n\t}"              \
      : "+f"(v), "+f"(out))
#define LAST(Tt, Dt)                                   \
  asm("{\n\t.reg .pred p;\n\t"                         \
      "setp.gt.f32 p, %0, " #Tt ";\n\t"                \
      "@p add.f32 %1, %1, " #Dt ";\n\t}"               \
      : "+f"(v), "+f"(out))

static __device__ __forceinline__ float run1_scan(float x) {
    float v = fabsf(x) - 0.8721661f;    // peeled step 0 (z0=1): v = |x| - h1
    float out = 0.0931013f;             // d0
    STEP(-0.35691947,  0.09543603, -0.9177631);
    STEP( 0.35702407, -0.00957536, -0.9392744);
    STEP( 1.8097845,  -0.02775419, -0.5681609);
    STEP(-0.8933508,   0.07635077, -0.9465831);
    STEP( 0.74517566, -0.02604962, -0.6847087);
    STEP( 0.57702994, -0.01608226, -0.45589155);
    STEP( 0.56928945, -0.0154707,  -0.57916474);
    STEP( 0.61470956, -0.01741009, -0.7803396);
    STEP( 0.43903926, -0.00761568, -0.28270212);
    STEP( 0.20668195, -0.00868225, -0.49239117);
    STEP( 0.6593264,  -0.01600825, -1.1224731);
    STEP( 0.35631987, -0.00795393, -0.5738949);
    STEP( 0.15981139, -0.0046836,  -0.32048506);
    STEP(-0.12464668, -0.00339996, -0.2620882);
    LAST(-0.22194518, -0.00177163);
    float r = copysignf(out, x);
    return (x == 0.0f) ? 0.0f : r;
}

static __device__ __forceinline__ float4 run4_table(float4 p) {
    float4 r;
    r.x = run1_table(p.x); r.y = run1_table(p.y);
    r.z = run1_table(p.z); r.w = run1_table(p.w);
    return r;
}
static __device__ __forceinline__ float4 run4_scan(float4 p) {
    float4 r;
    r.x = run1_scan(p.x); r.y = run1_scan(p.y);
    r.z = run1_scan(p.z); r.w = run1_scan(p.w);
    return r;
}

static __device__ __forceinline__ float amax4(float4 p) {
    return fmaxf(fmaxf(fabsf(p.x), fabsf(p.y)), fmaxf(fabsf(p.z), fabsf(p.w)));
}

// Exact-cover variant: grid covers nvec exactly, no bounds checks. 2 float4/thread.
__global__ void __launch_bounds__(512)
invert_kernel_exact(const float4* __restrict__ x, float4* __restrict__ y) {
    const int stride = blockDim.x * gridDim.x;
    const int i = blockIdx.x * blockDim.x + threadIdx.x;

    // Front-batched streaming loads (MLP_p1=2); data read once -> .cs
    float4 a0 = __ldcs(x + i);
    float4 a1 = __ldcs(x + i + stride);

    float mx = fmaxf(amax4(a0), amax4(a1));
    // Warp-uniform path select: slow warp iff ANY of its 256 elems >= CUT.
    if (__any_sync(0xFFFFFFFFu, mx >= ct::CUT)) {
        __stcs(y + i,          run4_scan(a0));
        __stcs(y + i + stride, run4_scan(a1));
    } else {
        __stcs(y + i,          run4_table(a0));
        __stcs(y + i + stride, run4_table(a1));
    }
}

// Guarded fallback for non-divisible sizes (exact scan everywhere; rare).
__global__ void __launch_bounds__(512)
invert_kernel_guard(const float4* __restrict__ x, float4* __restrict__ y, int nvec) {
    const int stride = blockDim.x * gridDim.x;
    const int i = blockIdx.x * blockDim.x + threadIdx.x;
    const int i0 = i, i1 = i + stride;

    float4 a0, a1;
    const bool m0 = (i0 < nvec), m1 = (i1 < nvec);
    if (m0) a0 = __ldcs(x + i0);
    if (m1) a1 = __ldcs(x + i1);

    if (m0) __stcs(y + i0, run4_scan(a0));
    if (m1) __stcs(y + i1, run4_scan(a1));
}

__global__ void invert_tail_kernel(const float* __restrict__ x, float* __restrict__ y,
                                   int start, int n) {
    int i = start + blockIdx.x * blockDim.x + threadIdx.x;
    if (i < n) y[i] = run1_scan(x[i]);
}

extern "C" void kernel_launch(void* const* d_in, const int* in_sizes, int n_in,
                              void* d_out, int out_size) {
    const float* x = (const float*)d_in[0];
    float* y = (float*)d_out;
    const long long n = (long long)in_sizes[0];

    const long long nvec = n >> 2;        // float4 count
    const int threads = 512;
    const int vpt = 2;                    // float4 per thread
    const long long per_blk = (long long)threads * vpt;

    if (nvec > 0 && (nvec % per_blk) == 0) {
        invert_kernel_exact<<<(unsigned)(nvec / per_blk), threads>>>(
            (const float4*)x, (float4*)y);
    } else if (nvec > 0) {
        long long blocks = (nvec + per_blk - 1) / per_blk;
        invert_kernel_guard<<<(unsigned)blocks, threads>>>(
            (const float4*)x, (float4*)y, (int)nvec);
    }

    const int rem = (int)(n & 3LL);
    if (rem) {
        invert_tail_kernel<<<1, 32>>>(x, y, (int)(n - rem), (int)n);
    }
}